// round 1
// baseline (speedup 1.0000x reference)
#include <cuda_runtime.h>
#include <math.h>

// Problem constants: L=K=KB=512, B=1, BATCH=16, C=2L=1024
#define BATCH 16
#define D 512            // L == K == KB
#define C2 1024          // conv channels (2L)
#define K3 3072          // conv GEMM K = 1024 channels * 3 taps

// ---------------- scratch (device globals; no allocation) ----------------
__device__ float g_Xe[BATCH * D * D];
__device__ float g_Se[BATCH * D * D];
__device__ float g_Ax[BATCH * D * D];
__device__ float g_As[BATCH * D * D];
__device__ float g_Xa[BATCH * D * D];
__device__ float g_Sa[BATCH * D * D];
__device__ float g_Mx[BATCH * D * D];
__device__ float g_Ms[BATCH * D * D];
__device__ float g_Xh[BATCH * C2 * D];
__device__ float g_Sh[BATCH * C2 * D];
__device__ float g_Wpx[K3 * C2];
__device__ float g_Wps[K3 * C2];

// ---------------- 512x512x512 SGEMM, 128x128 tile, 8x8 per thread ----------------
// C[b] = op(A[b]) @ B[b]; TRANSA: C = A^T B with A stored (K x M) row-major.
template<bool TRANSA>
__global__ __launch_bounds__(256, 2)
void sgemm512(const float* __restrict__ A, const float* __restrict__ B,
              float* __restrict__ Cm,
              long long sA, long long sB, long long sC)
{
    const int bM = blockIdx.y * 128;
    const int bN = blockIdx.x * 128;
    A += (long long)blockIdx.z * sA;
    B += (long long)blockIdx.z * sB;
    Cm += (long long)blockIdx.z * sC;

    __shared__ float As[8][128];
    __shared__ float Bs[8][128];

    const int tid = threadIdx.x;
    const int tr = tid >> 4;     // 0..15
    const int tc = tid & 15;     // 0..15

    float acc[8][8];
#pragma unroll
    for (int i = 0; i < 8; i++)
#pragma unroll
        for (int j = 0; j < 8; j++) acc[i][j] = 0.f;

    for (int k0 = 0; k0 < D; k0 += 8) {
        if (TRANSA) {
            const int kk = tid >> 5, m4 = (tid & 31) * 4;
            *(float4*)&As[kk][m4] = *(const float4*)&A[(long long)(k0 + kk) * D + bM + m4];
        } else {
            const int row = tid >> 1, seg = (tid & 1) * 4;
            const float4 v = *(const float4*)&A[(long long)(bM + row) * D + k0 + seg];
            As[seg + 0][row] = v.x; As[seg + 1][row] = v.y;
            As[seg + 2][row] = v.z; As[seg + 3][row] = v.w;
        }
        {
            const int kk = tid >> 5, n4 = (tid & 31) * 4;
            *(float4*)&Bs[kk][n4] = *(const float4*)&B[(long long)(k0 + kk) * D + bN + n4];
        }
        __syncthreads();
#pragma unroll
        for (int kk = 0; kk < 8; kk++) {
            float a[8], bb[8];
            *(float4*)&a[0]  = *(float4*)&As[kk][tr * 8];
            *(float4*)&a[4]  = *(float4*)&As[kk][tr * 8 + 4];
            *(float4*)&bb[0] = *(float4*)&Bs[kk][tc * 8];
            *(float4*)&bb[4] = *(float4*)&Bs[kk][tc * 8 + 4];
#pragma unroll
            for (int i = 0; i < 8; i++)
#pragma unroll
                for (int j = 0; j < 8; j++)
                    acc[i][j] = fmaf(a[i], bb[j], acc[i][j]);
        }
        __syncthreads();
    }

#pragma unroll
    for (int i = 0; i < 8; i++) {
        float* dst = &Cm[(long long)(bM + tr * 8 + i) * D + bN + tc * 8];
        *(float4*)&dst[0] = make_float4(acc[i][0], acc[i][1], acc[i][2], acc[i][3]);
        *(float4*)&dst[4] = make_float4(acc[i][4], acc[i][5], acc[i][6], acc[i][7]);
    }
}

// ---------------- row softmax over 512-wide contiguous rows ----------------
__global__ void softmax_rows(float* __restrict__ G)
{
    float* row = G + (long long)blockIdx.x * D;
    const int t = threadIdx.x;           // 256 threads
    const int lane = t & 31, w = t >> 5; // 8 warps

    float v0 = row[t], v1 = row[t + 256];
    __shared__ float sh[8];

    // max
    float m = fmaxf(v0, v1);
#pragma unroll
    for (int o = 16; o > 0; o >>= 1) m = fmaxf(m, __shfl_xor_sync(0xffffffffu, m, o));
    if (lane == 0) sh[w] = m;
    __syncthreads();
    if (w == 0) {
        float x = (lane < 8) ? sh[lane] : -INFINITY;
#pragma unroll
        for (int o = 4; o > 0; o >>= 1) x = fmaxf(x, __shfl_xor_sync(0xffffffffu, x, o));
        if (lane == 0) sh[0] = x;
    }
    __syncthreads();
    const float M = sh[0];
    __syncthreads();

    // sum
    float e0 = expf(v0 - M), e1 = expf(v1 - M);
    float s = e0 + e1;
#pragma unroll
    for (int o = 16; o > 0; o >>= 1) s += __shfl_xor_sync(0xffffffffu, s, o);
    if (lane == 0) sh[w] = s;
    __syncthreads();
    if (w == 0) {
        float x = (lane < 8) ? sh[lane] : 0.f;
#pragma unroll
        for (int o = 4; o > 0; o >>= 1) x += __shfl_xor_sync(0xffffffffu, x, o);
        if (lane == 0) sh[0] = x;
    }
    __syncthreads();
    const float inv = 1.f / sh[0];

    row[t] = e0 * inv;
    row[t + 256] = e1 * inv;
}

// ---------------- build X_hat / S_hat : (b, 1024, 512) ----------------
// Hat[b,c,k] = (c<512 ? M[b,c,k]*In[b,c,k] : In[b,c-512,k]) (+ sin(k) if addPos)
__global__ void build_hat(const float* __restrict__ Mm, const float* __restrict__ In,
                          float* __restrict__ Hat, int addPos)
{
    long long i = (long long)blockIdx.x * blockDim.x + threadIdx.x;
    const long long total = (long long)BATCH * C2 * D;
    if (i >= total) return;
    int k = (int)(i % D);
    long long r = i / D;
    int c = (int)(r % C2);
    long long b = r / C2;
    long long base = b * D * D + (long long)(c & (D - 1)) * D + k;
    float x = In[base];
    float v = (c < D) ? Mm[base] * x : x;
    if (addPos) v += sinf((float)k);
    Hat[i] = v;
}

// ---------------- pack conv weights: Wp[(i*3+t)*1024 + o] = w[o,i,t,1] ----------------
__global__ void pack_w(const float* __restrict__ w, float* __restrict__ wp)
{
    __shared__ float tile[32][33];
    const int k0 = blockIdx.x * 32;   // k3 = i*3+t, 0..3071
    const int o0 = blockIdx.y * 32;   // o, 0..1023
    const int tx = threadIdx.x, ty = threadIdx.y;  // 32 x 8
#pragma unroll
    for (int r = 0; r < 32; r += 8)
        tile[ty + r][tx] = w[(long long)(o0 + ty + r) * 9216 + (long long)(k0 + tx) * 3 + 1];
    __syncthreads();
#pragma unroll
    for (int r = 0; r < 32; r += 8)
        wp[(long long)(k0 + ty + r) * C2 + o0 + tx] = tile[tx][ty + r];
}

// ---------------- conv as implicit GEMM: Out[o,h] = bias[o] + sum_k3 Wp[k3][o]*In[i][h+t-1]
__global__ __launch_bounds__(256, 2)
void conv3(const float* __restrict__ Wp, const float* __restrict__ In,
           const float* __restrict__ bias, float* __restrict__ Out, int chanOff)
{
    const int bM = blockIdx.y * 128;   // o
    const int bN = blockIdx.x * 128;   // h
    const float* Inb = In + (long long)blockIdx.z * C2 * D;
    float* Outb = Out + (long long)blockIdx.z * 2048 * D + (long long)chanOff * D;

    __shared__ float As[8][128];
    __shared__ float Bs[8][128];

    const int tid = threadIdx.x;
    const int tr = tid >> 4, tc = tid & 15;
    const int kk = tid >> 5, seg4 = (tid & 31) * 4;

    float acc[8][8];
#pragma unroll
    for (int i = 0; i < 8; i++)
#pragma unroll
        for (int j = 0; j < 8; j++) acc[i][j] = 0.f;

    for (int k0 = 0; k0 < K3; k0 += 8) {
        // A: packed weights (coalesced)
        *(float4*)&As[kk][seg4] = *(const float4*)&Wp[(long long)(k0 + kk) * C2 + bM + seg4];
        // B: shifted input rows with zero pad
        {
            const int k3 = k0 + kk;
            const int ci = k3 / 3;
            const int t  = k3 - ci * 3;
            const float* src = Inb + (long long)ci * D;
#pragma unroll
            for (int r = 0; r < 4; r++) {
                const int h = bN + seg4 + r + t - 1;
                Bs[kk][seg4 + r] = (h >= 0 && h < D) ? src[h] : 0.f;
            }
        }
        __syncthreads();
#pragma unroll
        for (int q = 0; q < 8; q++) {
            float a[8], bb[8];
            *(float4*)&a[0]  = *(float4*)&As[q][tr * 8];
            *(float4*)&a[4]  = *(float4*)&As[q][tr * 8 + 4];
            *(float4*)&bb[0] = *(float4*)&Bs[q][tc * 8];
            *(float4*)&bb[4] = *(float4*)&Bs[q][tc * 8 + 4];
#pragma unroll
            for (int i = 0; i < 8; i++)
#pragma unroll
                for (int j = 0; j < 8; j++)
                    acc[i][j] = fmaf(a[i], bb[j], acc[i][j]);
        }
        __syncthreads();
    }

#pragma unroll
    for (int i = 0; i < 8; i++) {
        const float bo = bias[bM + tr * 8 + i];
        float* dst = &Outb[(long long)(bM + tr * 8 + i) * D + bN + tc * 8];
        *(float4*)&dst[0] = make_float4(acc[i][0] + bo, acc[i][1] + bo, acc[i][2] + bo, acc[i][3] + bo);
        *(float4*)&dst[4] = make_float4(acc[i][4] + bo, acc[i][5] + bo, acc[i][6] + bo, acc[i][7] + bo);
    }
}

// ---------------- launcher ----------------
extern "C" void kernel_launch(void* const* d_in, const int* in_sizes, int n_in,
                              void* d_out, int out_size)
{
    const float* X   = (const float*)d_in[0];
    const float* S   = (const float*)d_in[1];
    const float* W1x = (const float*)d_in[2];
    const float* W1s = (const float*)d_in[3];
    const float* W2x = (const float*)d_in[4];
    const float* W2s = (const float*)d_in[5];
    const float* cwx = (const float*)d_in[6];
    const float* cbx = (const float*)d_in[7];
    const float* cws = (const float*)d_in[8];
    const float* cbs = (const float*)d_in[9];
    float* out = (float*)d_out;

    float *Xe, *Se, *Ax, *As_, *Xa, *Sa, *Mx, *Ms, *Xh, *Sh, *Wpx, *Wps;
    cudaGetSymbolAddress((void**)&Xe,  g_Xe);
    cudaGetSymbolAddress((void**)&Se,  g_Se);
    cudaGetSymbolAddress((void**)&Ax,  g_Ax);
    cudaGetSymbolAddress((void**)&As_, g_As);
    cudaGetSymbolAddress((void**)&Xa,  g_Xa);
    cudaGetSymbolAddress((void**)&Sa,  g_Sa);
    cudaGetSymbolAddress((void**)&Mx,  g_Mx);
    cudaGetSymbolAddress((void**)&Ms,  g_Ms);
    cudaGetSymbolAddress((void**)&Xh,  g_Xh);
    cudaGetSymbolAddress((void**)&Sh,  g_Sh);
    cudaGetSymbolAddress((void**)&Wpx, g_Wpx);
    cudaGetSymbolAddress((void**)&Wps, g_Wps);

    const long long sF = (long long)D * D;
    const dim3 gG(4, 4, BATCH);

    // conv weight packing (independent; overlaps nothing but starts the stream)
    pack_w<<<dim3(K3 / 32, C2 / 32), dim3(32, 8)>>>(cwx, Wpx);
    pack_w<<<dim3(K3 / 32, C2 / 32), dim3(32, 8)>>>(cws, Wps);

    // projections (cross-wired): Xe = S@W1x, Se = X@W1s
    sgemm512<false><<<gG, 256>>>(S, W1x, Xe, sF, 0, sF);
    sgemm512<false><<<gG, 256>>>(X, W1s, Se, sF, 0, sF);

    // Gram matrices + softmax
    sgemm512<true><<<gG, 256>>>(Xe, Xe, Ax,  sF, sF, sF);
    sgemm512<true><<<gG, 256>>>(Se, Se, As_, sF, sF, sF);
    softmax_rows<<<BATCH * D, 256>>>(Ax);
    softmax_rows<<<BATCH * D, 256>>>(As_);

    // attention apply
    sgemm512<false><<<gG, 256>>>(Xe, Ax,  Xa, sF, sF, sF);
    sgemm512<false><<<gG, 256>>>(Se, As_, Sa, sF, sF, sF);

    // mix (B=1 -> plain GEMM with W2)
    sgemm512<false><<<gG, 256>>>(Xa, W2x, Mx, sF, 0, sF);
    sgemm512<false><<<gG, 256>>>(Sa, W2s, Ms, sF, 0, sF);

    // build conv inputs
    const long long totHat = (long long)BATCH * C2 * D;
    build_hat<<<(unsigned)((totHat + 255) / 256), 256>>>(Mx, X, Xh, 0);
    build_hat<<<(unsigned)((totHat + 255) / 256), 256>>>(Ms, S, Sh, 1);

    // convs -> output halves
    conv3<<<dim3(4, 8, BATCH), 256>>>(Wpx, Xh, cbx, out, 0);
    conv3<<<dim3(4, 8, BATCH), 256>>>(Wps, Sh, cbs, out, C2);
}